// round 1
// baseline (speedup 1.0000x reference)
#include <cuda_runtime.h>

// ---------------------------------------------------------------------------
// WindowAttentionConvRpe: Swin window attention with contextual RPE bias.
//   B=4096 windows, N=49 tokens, DIM=192, NH=6, HD=32, T=169, NW=64.
// Pipeline:
//   K1: QKV = X @ qkv_w + qkv_b        (q part pre-scaled by HD^-0.5)
//   K2: per-(window,head) attention with in-kernel RPE index computation
//   K3: OUT = O @ proj_w + proj_b
// Output buffer = [ out (B*49*192 floats) | attn (B*6*49*49 floats) ]
// ---------------------------------------------------------------------------

#define B_WIN   4096
#define NTOK    49
#define DIMC    192
#define NHEAD   6
#define HDIM    32
#define TSZ     169
#define TOKENS  (B_WIN * NTOK)          // 200704
#define QKVCOLS (3 * DIMC)              // 576
#define QSCALE  0.17677669529663687f    // 32^-0.5

// scratch (device globals: allocation-free rule)
__device__ float g_qkv [(size_t)TOKENS * QKVCOLS];   // 462 MB
__device__ float g_obuf[(size_t)TOKENS * DIMC];      // 154 MB

// ---------------------------------------------------------------------------
// K1/K3: C[M,N] = A[M,K] @ W[K,N] + bias[N]; columns < scale_limit get *scale.
// BM=128, BN=64, BK=16, 256 threads, 8x4 microtile. M%128==0, N%64==0, K%16==0.
// ---------------------------------------------------------------------------
__global__ __launch_bounds__(256) void gemm_bias_kernel(
    const float* __restrict__ A, const float* __restrict__ W,
    const float* __restrict__ bias, float* __restrict__ C,
    int M, int N, int K, int scale_limit, float scale)
{
    __shared__ float As[16][129];   // [k][m], padded
    __shared__ float Bs[16][64];    // [k][n]

    const int tid = threadIdx.x;
    const int tx = tid & 15;        // n-tile coord (16)
    const int ty = tid >> 4;        // m-tile coord (16)
    const int m0 = blockIdx.y * 128;
    const int n0 = blockIdx.x * 64;

    float acc[8][4];
    #pragma unroll
    for (int i = 0; i < 8; i++)
        #pragma unroll
        for (int j = 0; j < 4; j++) acc[i][j] = 0.0f;

    for (int k0 = 0; k0 < K; k0 += 16) {
        // A tile: 128x16 = 512 float4
        #pragma unroll
        for (int r = 0; r < 2; r++) {
            int f  = tid + r * 256;       // 0..511
            int m  = f >> 2;              // 0..127
            int k4 = (f & 3) * 4;         // 0,4,8,12
            float4 av = *(const float4*)(A + (size_t)(m0 + m) * K + k0 + k4);
            As[k4 + 0][m] = av.x; As[k4 + 1][m] = av.y;
            As[k4 + 2][m] = av.z; As[k4 + 3][m] = av.w;
        }
        // B tile: 16x64 = 256 float4
        {
            int kk = tid >> 4;            // 0..15
            int n4 = (tid & 15) * 4;      // 0..60
            *(float4*)&Bs[kk][n4] =
                *(const float4*)(W + (size_t)(k0 + kk) * N + n0 + n4);
        }
        __syncthreads();

        #pragma unroll
        for (int kk = 0; kk < 16; kk++) {
            float4 bv = *(float4*)&Bs[kk][tx * 4];
            float b0 = bv.x, b1 = bv.y, b2 = bv.z, b3 = bv.w;
            #pragma unroll
            for (int i = 0; i < 8; i++) {
                float a = As[kk][ty * 8 + i];
                acc[i][0] += a * b0;
                acc[i][1] += a * b1;
                acc[i][2] += a * b2;
                acc[i][3] += a * b3;
            }
        }
        __syncthreads();
    }

    #pragma unroll
    for (int i = 0; i < 8; i++) {
        int m = m0 + ty * 8 + i;
        #pragma unroll
        for (int j = 0; j < 4; j++) {
            int n = n0 + tx * 4 + j;
            float v = acc[i][j] + bias[n];
            if (n < scale_limit) v *= scale;
            C[(size_t)m * N + n] = v;
        }
    }
}

// ---------------------------------------------------------------------------
// K2: attention for one (window b, head h) per block, 128 threads (4 warps).
// Each warp owns rows i = warp, warp+4, ... Lanes cover keys j (j, j+32).
//   score[i,j] = q_i.k_j + q_i.Tq[:,t] + k_i.Tk[:,t] + mask[b%64,i,j]
//   t = (ri-rj+6)*13 + (ci-cj+6)   (recomputed; matches reference gather)
// Then per-row softmax (warp shuffles), write attn, then o = p @ v.
// ---------------------------------------------------------------------------
#define ATTN_SMEM_FLOATS (49*32 + 32*49 + 49*32 + 32*169 + 32*169 + 49*49)
#define ATTN_SMEM_BYTES  (ATTN_SMEM_FLOATS * 4)

__global__ __launch_bounds__(128) void attn_kernel(
    const float* __restrict__ mask,
    const float* __restrict__ q_rpe, const float* __restrict__ k_rpe,
    float* __restrict__ attn_out)
{
    extern __shared__ float sm[];
    float* q_s  = sm;                 // [49][32]  (q pre-scaled)
    float* kT_s = q_s  + 49 * 32;     // [32][49]  (d-major: conflict-free j reads)
    float* v_s  = kT_s + 32 * 49;     // [49][32]
    float* tqT  = v_s  + 49 * 32;     // [32][169] (d-major)
    float* tkT  = tqT  + 32 * 169;    // [32][169]
    float* p_s  = tkT  + 32 * 169;    // [49][49]

    const int h = blockIdx.x;
    const int b = blockIdx.y;
    const int tid  = threadIdx.x;
    const int lane = tid & 31;
    const int warp = tid >> 5;

    // load q,k,v for this (b,h)
    for (int idx = tid; idx < 49 * 32; idx += 128) {
        int i = idx >> 5, d = idx & 31;
        size_t row = ((size_t)b * 49 + i) * QKVCOLS;
        q_s[idx]         = g_qkv[row + h * 32 + d];
        kT_s[d * 49 + i] = g_qkv[row + 192 + h * 32 + d];
        v_s[idx]         = g_qkv[row + 384 + h * 32 + d];
    }
    // tables: head slab is contiguous (h, 32, 169) -> [d][t] layout directly
    {
        const float* tq = q_rpe + (size_t)h * 32 * 169;
        const float* tk = k_rpe + (size_t)h * 32 * 169;
        for (int idx = tid; idx < 32 * 169; idx += 128) {
            tqT[idx] = tq[idx];
            tkT[idx] = tk[idx];
        }
    }
    __syncthreads();

    const float* mrow = mask + (size_t)(b & 63) * (49 * 49);
    float* attn_b = attn_out + ((size_t)b * NHEAD + h) * (49 * 49);
    float* ob     = g_obuf + (size_t)b * 49 * DIMC + h * 32;

    for (int i = warp; i < 49; i += 4) {
        const int ri = i / 7, ci = i % 7;
        const int j1 = lane;
        const int j2 = lane + 32;
        const bool has2 = (j2 < 49);
        const int t1 = (ri - j1 / 7 + 6) * 13 + (ci - j1 % 7 + 6);
        const int t2 = has2 ? (ri - j2 / 7 + 6) * 13 + (ci - j2 % 7 + 6) : 0;

        float acc1 = 0.0f, acc2 = 0.0f;
        #pragma unroll 8
        for (int d = 0; d < 32; d++) {
            float qd  = q_s[i * 32 + d];          // broadcast
            float kid = kT_s[d * 49 + i];         // broadcast
            float kj1 = kT_s[d * 49 + j1];        // conflict-free
            float tq1 = tqT[d * 169 + t1];
            float tk1 = tkT[d * 169 + t1];
            acc1 += qd * (kj1 + tq1) + kid * tk1;
            if (has2) {
                float kj2 = kT_s[d * 49 + j2];
                float tq2 = tqT[d * 169 + t2];
                float tk2 = tkT[d * 169 + t2];
                acc2 += qd * (kj2 + tq2) + kid * tk2;
            }
        }
        acc1 += mrow[i * 49 + j1];
        if (has2) acc2 += mrow[i * 49 + j2];

        // softmax over 49 keys spread across lanes
        float mx = has2 ? fmaxf(acc1, acc2) : acc1;
        #pragma unroll
        for (int o = 16; o > 0; o >>= 1)
            mx = fmaxf(mx, __shfl_xor_sync(0xffffffffu, mx, o));
        float e1 = expf(acc1 - mx);
        float e2 = has2 ? expf(acc2 - mx) : 0.0f;
        float sum = e1 + e2;
        #pragma unroll
        for (int o = 16; o > 0; o >>= 1)
            sum += __shfl_xor_sync(0xffffffffu, sum, o);
        float inv = 1.0f / sum;
        float p1 = e1 * inv, p2 = e2 * inv;

        p_s[i * 49 + j1]    = p1;
        attn_b[i * 49 + j1] = p1;
        if (has2) { p_s[i * 49 + j2] = p2; attn_b[i * 49 + j2] = p2; }
        __syncwarp();

        // o[i][d=lane] = sum_j p[i,j] * v[j,d]
        float o_acc = 0.0f;
        #pragma unroll 7
        for (int j = 0; j < 49; j++)
            o_acc += p_s[i * 49 + j] * v_s[j * 32 + lane];
        ob[(size_t)i * DIMC + lane] = o_acc;
    }
}

// ---------------------------------------------------------------------------
extern "C" void kernel_launch(void* const* d_in, const int* in_sizes, int n_in,
                              void* d_out, int out_size)
{
    const float* x      = (const float*)d_in[0];
    const float* mask   = (const float*)d_in[1];
    const float* qkv_w  = (const float*)d_in[2];
    const float* qkv_b  = (const float*)d_in[3];
    const float* q_rpe  = (const float*)d_in[4];
    const float* k_rpe  = (const float*)d_in[5];
    const float* proj_w = (const float*)d_in[6];
    const float* proj_b = (const float*)d_in[7];
    // d_in[8] = rpe_indices: recomputed analytically in-kernel (dtype-agnostic)

    float* out  = (float*)d_out;
    float* attn = out + (size_t)TOKENS * DIMC;   // out tuple: (out, attn) concatenated

    void* qkv_ptr  = nullptr;
    void* obuf_ptr = nullptr;
    cudaGetSymbolAddress(&qkv_ptr,  g_qkv);
    cudaGetSymbolAddress(&obuf_ptr, g_obuf);

    // K1: QKV projection (q columns pre-scaled by 32^-0.5, after bias — matches ref)
    {
        dim3 grid(QKVCOLS / 64, TOKENS / 128);
        gemm_bias_kernel<<<grid, 256>>>(x, qkv_w, qkv_b, (float*)qkv_ptr,
                                        TOKENS, QKVCOLS, DIMC, DIMC, QSCALE);
    }

    // K2: attention
    {
        cudaFuncSetAttribute(attn_kernel,
                             cudaFuncAttributeMaxDynamicSharedMemorySize,
                             ATTN_SMEM_BYTES);
        dim3 grid(NHEAD, B_WIN);
        attn_kernel<<<grid, 128, ATTN_SMEM_BYTES>>>(mask, q_rpe, k_rpe, attn);
    }

    // K3: output projection
    {
        dim3 grid(DIMC / 64, TOKENS / 128);
        gemm_bias_kernel<<<grid, 256>>>((const float*)obuf_ptr, proj_w, proj_b, out,
                                        TOKENS, DIMC, DIMC, 0, 1.0f);
    }
}

// round 2
// speedup vs baseline: 1.2542x; 1.2542x over previous
#include <cuda_runtime.h>

// ---------------------------------------------------------------------------
// WindowAttentionConvRpe: Swin window attention with contextual RPE bias.
//   B=4096 windows, N=49 tokens, DIM=192, NH=6, HD=32, T=169, NW=64.
// ---------------------------------------------------------------------------

#define B_WIN   4096
#define NTOK    49
#define DIMC    192
#define NHEAD   6
#define HDIM    32
#define TSZ     169
#define TOKENS  (B_WIN * NTOK)          // 200704
#define QKVCOLS (3 * DIMC)              // 576
#define QSCALE  0.17677669529663687f    // 32^-0.5

// scratch (device globals: allocation-free rule)
__device__ float g_qkv [(size_t)TOKENS * QKVCOLS];
__device__ float g_obuf[(size_t)TOKENS * DIMC];

// ---------------------------------------------------------------------------
// K1/K3: C[M,N] = A[M,K] @ W[K,N] + bias[N]; cols < scale_limit get *scale.
// BM=128, BN=64, BK=16, 128 threads, 8x8 microtile (split 4+4 rows / 4+4 cols
// for conflict-free LDS.128). M%128==0, N%64==0, K%16==0.
// ---------------------------------------------------------------------------
__global__ __launch_bounds__(128) void gemm_bias_kernel(
    const float* __restrict__ A, const float* __restrict__ W,
    const float* __restrict__ bias, float* __restrict__ C,
    int M, int N, int K, int scale_limit, float scale)
{
    __shared__ float As[16][132];   // [k][m], padded
    __shared__ float Bs[16][64];    // [k][n]

    const int tid = threadIdx.x;
    const int tx = tid & 7;         // 8 col-threads, each owns cols {tx*4..+3, 32+tx*4..+3}
    const int ty = tid >> 3;        // 16 row-threads, each owns rows {ty*4..+3, 64+ty*4..+3}
    const int m0 = blockIdx.y * 128;
    const int n0 = blockIdx.x * 64;

    float acc[8][8];
    #pragma unroll
    for (int i = 0; i < 8; i++)
        #pragma unroll
        for (int j = 0; j < 8; j++) acc[i][j] = 0.0f;

    for (int k0 = 0; k0 < K; k0 += 16) {
        // A tile: 128x16 = 512 float4, 4 per thread (transposed into As[k][m])
        #pragma unroll
        for (int r = 0; r < 4; r++) {
            int f  = tid + r * 128;
            int m  = f >> 2;
            int k4 = (f & 3) * 4;
            float4 av = *(const float4*)(A + (size_t)(m0 + m) * K + k0 + k4);
            As[k4 + 0][m] = av.x; As[k4 + 1][m] = av.y;
            As[k4 + 2][m] = av.z; As[k4 + 3][m] = av.w;
        }
        // B tile: 16x64 = 256 float4, 2 per thread
        #pragma unroll
        for (int r = 0; r < 2; r++) {
            int f  = tid + r * 128;
            int kk = f >> 4;
            int n4 = (f & 15) * 4;
            *(float4*)&Bs[kk][n4] =
                *(const float4*)(W + (size_t)(k0 + kk) * N + n0 + n4);
        }
        __syncthreads();

        #pragma unroll
        for (int kk = 0; kk < 16; kk++) {
            float4 a0 = *(float4*)&As[kk][ty * 4];        // broadcast within phase
            float4 a1 = *(float4*)&As[kk][64 + ty * 4];
            float4 b0 = *(float4*)&Bs[kk][tx * 4];        // 8 distinct 16B chunks
            float4 b1 = *(float4*)&Bs[kk][32 + tx * 4];
            float a[8] = {a0.x, a0.y, a0.z, a0.w, a1.x, a1.y, a1.z, a1.w};
            float b[8] = {b0.x, b0.y, b0.z, b0.w, b1.x, b1.y, b1.z, b1.w};
            #pragma unroll
            for (int i = 0; i < 8; i++)
                #pragma unroll
                for (int j = 0; j < 8; j++)
                    acc[i][j] += a[i] * b[j];
        }
        __syncthreads();
    }

    #pragma unroll
    for (int i = 0; i < 8; i++) {
        int m = m0 + ((i < 4) ? (ty * 4 + i) : (64 + ty * 4 + (i - 4)));
        #pragma unroll
        for (int jh = 0; jh < 2; jh++) {
            int nb = n0 + jh * 32 + tx * 4;
            float4 ov;
            float* ap = &acc[i][jh * 4];
            float4 bv = *(const float4*)(bias + nb);
            ov.x = ap[0] + bv.x; ov.y = ap[1] + bv.y;
            ov.z = ap[2] + bv.z; ov.w = ap[3] + bv.w;
            if (nb + 3 < scale_limit) {
                ov.x *= scale; ov.y *= scale; ov.z *= scale; ov.w *= scale;
            }
            *(float4*)(C + (size_t)m * N + nb) = ov;
        }
    }
}

// ---------------------------------------------------------------------------
// K2: attention, one (window b, head h) per block, 256 threads (8 warps).
// Warp owns rows i = warp, warp+8, ... Lanes cover keys j (j, j+32).
//   score[i,j] = q_i.k_j + q_i.Tq[:,t] + k_i.Tk[:,t] + mask[b%64,i,j]
//   t = (ri-rj+6)*13 + (ci-cj+6)
// ---------------------------------------------------------------------------
#define ATTN_SMEM_FLOATS (49*32 + 32*49 + 49*32 + 32*169 + 32*169 + 49*49)
#define ATTN_SMEM_BYTES  (ATTN_SMEM_FLOATS * 4)

__global__ __launch_bounds__(256) void attn_kernel(
    const float* __restrict__ mask,
    const float* __restrict__ q_rpe, const float* __restrict__ k_rpe,
    float* __restrict__ attn_out)
{
    extern __shared__ float sm[];
    float* q_s  = sm;                 // [49][32]  (q pre-scaled)
    float* kT_s = q_s  + 49 * 32;     // [32][49]  (d-major)
    float* v_s  = kT_s + 32 * 49;     // [49][32]
    float* tqT  = v_s  + 49 * 32;     // [32][169] (d-major)
    float* tkT  = tqT  + 32 * 169;    // [32][169]
    float* p_s  = tkT  + 32 * 169;    // [49][49]

    const int h = blockIdx.x;
    const int b = blockIdx.y;
    const int tid  = threadIdx.x;
    const int lane = tid & 31;
    const int warp = tid >> 5;

    // stage q,k,v (float4 where possible; k transposed elementwise)
    for (int idx = tid; idx < 49 * 8; idx += 256) {
        int i = idx >> 3, c4 = (idx & 7) * 4;
        size_t row = ((size_t)b * 49 + i) * QKVCOLS + h * 32;
        float4 qv = *(const float4*)(g_qkv + row + c4);
        *(float4*)(q_s + i * 32 + c4) = qv;
        float4 vv = *(const float4*)(g_qkv + row + 384 + c4);
        *(float4*)(v_s + i * 32 + c4) = vv;
        float4 kv = *(const float4*)(g_qkv + row + 192 + c4);
        kT_s[(c4 + 0) * 49 + i] = kv.x;
        kT_s[(c4 + 1) * 49 + i] = kv.y;
        kT_s[(c4 + 2) * 49 + i] = kv.z;
        kT_s[(c4 + 3) * 49 + i] = kv.w;
    }
    // tables: contiguous (32,169) slab per head -> float4 copy (5408/4 = 1352)
    {
        const float4* tq = (const float4*)(q_rpe + (size_t)h * 32 * 169);
        const float4* tk = (const float4*)(k_rpe + (size_t)h * 32 * 169);
        for (int idx = tid; idx < 1352; idx += 256) {
            ((float4*)tqT)[idx] = tq[idx];
            ((float4*)tkT)[idx] = tk[idx];
        }
    }
    __syncthreads();

    const float* mrow = mask + (size_t)(b & 63) * (49 * 49);
    float* attn_b = attn_out + ((size_t)b * NHEAD + h) * (49 * 49);
    float* ob     = g_obuf + (size_t)b * 49 * DIMC + h * 32;

    for (int i = warp; i < 49; i += 8) {
        const int ri = i / 7, ci = i % 7;
        const int j1 = lane;
        const int j2 = lane + 32;
        const bool has2 = (j2 < 49);
        const int t1 = (ri - j1 / 7 + 6) * 13 + (ci - j1 % 7 + 6);
        const int t2 = has2 ? (ri - j2 / 7 + 6) * 13 + (ci - j2 % 7 + 6) : 0;

        float acc1 = 0.0f, acc2 = 0.0f;
        #pragma unroll 16
        for (int d = 0; d < 32; d++) {
            float qd  = q_s[i * 32 + d];
            float kid = kT_s[d * 49 + i];
            float kj1 = kT_s[d * 49 + j1];
            float tq1 = tqT[d * 169 + t1];
            float tk1 = tkT[d * 169 + t1];
            acc1 += qd * (kj1 + tq1) + kid * tk1;
            if (has2) {
                float kj2 = kT_s[d * 49 + j2];
                float tq2 = tqT[d * 169 + t2];
                float tk2 = tkT[d * 169 + t2];
                acc2 += qd * (kj2 + tq2) + kid * tk2;
            }
        }
        acc1 += mrow[i * 49 + j1];
        if (has2) acc2 += mrow[i * 49 + j2];

        float mx = has2 ? fmaxf(acc1, acc2) : acc1;
        #pragma unroll
        for (int o = 16; o > 0; o >>= 1)
            mx = fmaxf(mx, __shfl_xor_sync(0xffffffffu, mx, o));
        float e1 = __expf(acc1 - mx);
        float e2 = has2 ? __expf(acc2 - mx) : 0.0f;
        float sum = e1 + e2;
        #pragma unroll
        for (int o = 16; o > 0; o >>= 1)
            sum += __shfl_xor_sync(0xffffffffu, sum, o);
        float inv = 1.0f / sum;
        float p1 = e1 * inv, p2 = e2 * inv;

        p_s[i * 49 + j1]    = p1;
        attn_b[i * 49 + j1] = p1;
        if (has2) { p_s[i * 49 + j2] = p2; attn_b[i * 49 + j2] = p2; }
        __syncwarp();

        // o[i][d=lane] = sum_j p[i,j] * v[j,d]
        float o_acc = 0.0f;
        #pragma unroll 7
        for (int j = 0; j < 49; j++)
            o_acc += p_s[i * 49 + j] * v_s[j * 32 + lane];
        ob[(size_t)i * DIMC + lane] = o_acc;
    }
}

// ---------------------------------------------------------------------------
extern "C" void kernel_launch(void* const* d_in, const int* in_sizes, int n_in,
                              void* d_out, int out_size)
{
    const float* x      = (const float*)d_in[0];
    const float* mask   = (const float*)d_in[1];
    const float* qkv_w  = (const float*)d_in[2];
    const float* qkv_b  = (const float*)d_in[3];
    const float* q_rpe  = (const float*)d_in[4];
    const float* k_rpe  = (const float*)d_in[5];
    const float* proj_w = (const float*)d_in[6];
    const float* proj_b = (const float*)d_in[7];
    // d_in[8] = rpe_indices: recomputed analytically in-kernel

    float* out  = (float*)d_out;
    float* attn = out + (size_t)TOKENS * DIMC;

    void* qkv_ptr  = nullptr;
    void* obuf_ptr = nullptr;
    cudaGetSymbolAddress(&qkv_ptr,  g_qkv);
    cudaGetSymbolAddress(&obuf_ptr, g_obuf);

    // K1: QKV projection (q columns pre-scaled by 32^-0.5)
    {
        dim3 grid(QKVCOLS / 64, TOKENS / 128);
        gemm_bias_kernel<<<grid, 128>>>(x, qkv_w, qkv_b, (float*)qkv_ptr,
                                        TOKENS, QKVCOLS, DIMC, DIMC, QSCALE);
    }

    // K2: attention
    {
        cudaFuncSetAttribute(attn_kernel,
                             cudaFuncAttributeMaxDynamicSharedMemorySize,
                             ATTN_SMEM_BYTES);
        dim3 grid(NHEAD, B_WIN);
        attn_kernel<<<grid, 256, ATTN_SMEM_BYTES>>>(mask, q_rpe, k_rpe, attn);
    }

    // K3: output projection
    {
        dim3 grid(DIMC / 64, TOKENS / 128);
        gemm_bias_kernel<<<grid, 128>>>((const float*)obuf_ptr, proj_w, proj_b, out,
                                        TOKENS, DIMC, DIMC, 0, 1.0f);
    }
}

// round 3
// speedup vs baseline: 1.4135x; 1.1270x over previous
#include <cuda_runtime.h>

// ---------------------------------------------------------------------------
// WindowAttentionConvRpe: B=4096 windows, N=49, DIM=192, NH=6, HD=32, T=169.
// Pipeline:
//   K1 : QKV = X @ qkv_w + qkv_b   (q pre-scaled)
//   K2a: BIAS[b,h,i,j] = [q;k]_{b,h,i} . G_{h,i}[:,j]   (batched GEMM,
//        G = gathered RPE table columns, shared across all 4096 windows)
//   K2b: attention: S = qk + BIAS + mask -> softmax -> O = P V
//   K3 : OUT = O @ proj_w + proj_b
// ---------------------------------------------------------------------------

#define B_WIN   4096
#define NTOK    49
#define DIMC    192
#define NHEAD   6
#define HDIM    32
#define TSZ     169
#define TOKENS  (B_WIN * NTOK)
#define QKVCOLS (3 * DIMC)
#define QSCALE  0.17677669529663687f

__device__ float g_qkv [(size_t)TOKENS * QKVCOLS];
__device__ float g_obuf[(size_t)TOKENS * DIMC];
__device__ float g_bias[(size_t)B_WIN * NHEAD * NTOK * NTOK];

// ---------------------------------------------------------------------------
// K1/K3: C[M,N] = A[M,K] @ W[K,N] + bias[N]; cols < scale_limit get *scale.
// ---------------------------------------------------------------------------
__global__ __launch_bounds__(128) void gemm_bias_kernel(
    const float* __restrict__ A, const float* __restrict__ W,
    const float* __restrict__ bias, float* __restrict__ C,
    int M, int N, int K, int scale_limit, float scale)
{
    __shared__ float As[16][132];
    __shared__ float Bs[16][64];

    const int tid = threadIdx.x;
    const int tx = tid & 7;
    const int ty = tid >> 3;
    const int m0 = blockIdx.y * 128;
    const int n0 = blockIdx.x * 64;

    float acc[8][8];
    #pragma unroll
    for (int i = 0; i < 8; i++)
        #pragma unroll
        for (int j = 0; j < 8; j++) acc[i][j] = 0.0f;

    for (int k0 = 0; k0 < K; k0 += 16) {
        #pragma unroll
        for (int r = 0; r < 4; r++) {
            int f  = tid + r * 128;
            int m  = f >> 2;
            int k4 = (f & 3) * 4;
            float4 av = *(const float4*)(A + (size_t)(m0 + m) * K + k0 + k4);
            As[k4 + 0][m] = av.x; As[k4 + 1][m] = av.y;
            As[k4 + 2][m] = av.z; As[k4 + 3][m] = av.w;
        }
        #pragma unroll
        for (int r = 0; r < 2; r++) {
            int f  = tid + r * 128;
            int kk = f >> 4;
            int n4 = (f & 15) * 4;
            *(float4*)&Bs[kk][n4] =
                *(const float4*)(W + (size_t)(k0 + kk) * N + n0 + n4);
        }
        __syncthreads();

        #pragma unroll
        for (int kk = 0; kk < 16; kk++) {
            float4 a0 = *(float4*)&As[kk][ty * 4];
            float4 a1 = *(float4*)&As[kk][64 + ty * 4];
            float4 b0 = *(float4*)&Bs[kk][tx * 4];
            float4 b1 = *(float4*)&Bs[kk][32 + tx * 4];
            float a[8] = {a0.x, a0.y, a0.z, a0.w, a1.x, a1.y, a1.z, a1.w};
            float b[8] = {b0.x, b0.y, b0.z, b0.w, b1.x, b1.y, b1.z, b1.w};
            #pragma unroll
            for (int i = 0; i < 8; i++)
                #pragma unroll
                for (int j = 0; j < 8; j++)
                    acc[i][j] += a[i] * b[j];
        }
        __syncthreads();
    }

    #pragma unroll
    for (int i = 0; i < 8; i++) {
        int m = m0 + ((i < 4) ? (ty * 4 + i) : (64 + ty * 4 + (i - 4)));
        #pragma unroll
        for (int jh = 0; jh < 2; jh++) {
            int nb = n0 + jh * 32 + tx * 4;
            float4 ov;
            float* ap = &acc[i][jh * 4];
            float4 bv = *(const float4*)(bias + nb);
            ov.x = ap[0] + bv.x; ov.y = ap[1] + bv.y;
            ov.z = ap[2] + bv.z; ov.w = ap[3] + bv.w;
            if (nb + 3 < scale_limit) {
                ov.x *= scale; ov.y *= scale; ov.z *= scale; ov.w *= scale;
            }
            *(float4*)(C + (size_t)m * N + nb) = ov;
        }
    }
}

// ---------------------------------------------------------------------------
// K2a: bias GEMM. Block = one (h,i) x 128-window tile.
//   BIAS[b,h,i,j] = sum_{d<32} q[b,h,i,d]*Tq[h,d,t(i,j)]
//                 + sum_{d<32} k[b,h,i,d]*Tk[h,d,t(i,j)]
// A_s[d][b] (64x128, d-major), G_s[d][j] (64x64, cols>=49 zero).
// 256 threads: ty=tid>>3 owns 4 b-rows, tx=tid&7 owns 8 j-cols.
// ---------------------------------------------------------------------------
__global__ __launch_bounds__(256) void bias_kernel(
    const float* __restrict__ q_rpe, const float* __restrict__ k_rpe)
{
    __shared__ float A_s[64][128];
    __shared__ float G_s[64][64];

    const int hi = blockIdx.x;           // 0..293
    const int h  = hi / NTOK;
    const int i  = hi % NTOK;
    const int ri = i / 7, ci = i % 7;
    const int m0 = blockIdx.y * 128;
    const int tid = threadIdx.x;

    // stage A: q part (d 0..31) and k part (d 32..63), bank-conflict-free
    for (int f = tid; f < 8 * 128; f += 256) {
        int bl = f & 127;
        int g4 = f >> 7;                  // 0..7 -> dims g4*4..g4*4+3
        size_t row = ((size_t)(m0 + bl) * NTOK + i) * QKVCOLS + h * HDIM;
        float4 qv = *(const float4*)(g_qkv + row + g4 * 4);
        A_s[g4 * 4 + 0][bl] = qv.x; A_s[g4 * 4 + 1][bl] = qv.y;
        A_s[g4 * 4 + 2][bl] = qv.z; A_s[g4 * 4 + 3][bl] = qv.w;
        float4 kv = *(const float4*)(g_qkv + row + DIMC + g4 * 4);
        A_s[32 + g4 * 4 + 0][bl] = kv.x; A_s[32 + g4 * 4 + 1][bl] = kv.y;
        A_s[32 + g4 * 4 + 2][bl] = kv.z; A_s[32 + g4 * 4 + 3][bl] = kv.w;
    }
    // stage G: gathered table columns (L2-hot, once per block not per window)
    for (int f = tid; f < 64 * 64; f += 256) {
        int d = f >> 6, j = f & 63;
        float val = 0.0f;
        if (j < NTOK) {
            int t = (ri - j / 7 + 6) * 13 + (ci - j % 7 + 6);
            val = (d < HDIM) ? q_rpe[(h * HDIM + d) * TSZ + t]
                             : k_rpe[(h * HDIM + (d - 32)) * TSZ + t];
        }
        G_s[d][j] = val;
    }
    __syncthreads();

    const int tx = tid & 7;
    const int ty = tid >> 3;

    float acc[4][8];
    #pragma unroll
    for (int r = 0; r < 4; r++)
        #pragma unroll
        for (int c = 0; c < 8; c++) acc[r][c] = 0.0f;

    #pragma unroll 16
    for (int d = 0; d < 64; d++) {
        float4 a4 = *(float4*)&A_s[d][ty * 4];
        float4 g0 = *(float4*)&G_s[d][tx * 8];
        float4 g1 = *(float4*)&G_s[d][tx * 8 + 4];
        float a[4] = {a4.x, a4.y, a4.z, a4.w};
        float g[8] = {g0.x, g0.y, g0.z, g0.w, g1.x, g1.y, g1.z, g1.w};
        #pragma unroll
        for (int r = 0; r < 4; r++)
            #pragma unroll
            for (int c = 0; c < 8; c++)
                acc[r][c] += a[r] * g[c];
    }

    #pragma unroll
    for (int r = 0; r < 4; r++) {
        int bw = m0 + ty * 4 + r;
        size_t base = (((size_t)bw * NHEAD + h) * NTOK + i) * NTOK;
        #pragma unroll
        for (int c = 0; c < 8; c++) {
            int j = tx * 8 + c;
            if (j < NTOK) g_bias[base + j] = acc[r][c];
        }
    }
}

// ---------------------------------------------------------------------------
// K2b: attention per (b,h). 256 threads, 8 warps; warp owns rows i=warp+8r.
// K held in registers (lane j covers keys j and j+32). Bias read from gmem.
// ---------------------------------------------------------------------------
__global__ __launch_bounds__(256) void attn2_kernel(
    const float* __restrict__ mask, float* __restrict__ attn_out)
{
    __shared__ float q_s[49 * 32];
    __shared__ float v_s[49 * 32];
    __shared__ float p_s[49 * 52];

    const int h = blockIdx.x;
    const int b = blockIdx.y;
    const int tid  = threadIdx.x;
    const int lane = tid & 31;
    const int warp = tid >> 5;

    // stage q, v (float4, coalesced-ish)
    for (int f = tid; f < 49 * 8; f += 256) {
        int i = f >> 3, c4 = (f & 7) * 4;
        size_t row = ((size_t)b * NTOK + i) * QKVCOLS + h * HDIM;
        *(float4*)(q_s + i * 32 + c4) = *(const float4*)(g_qkv + row + c4);
        *(float4*)(v_s + i * 32 + c4) = *(const float4*)(g_qkv + row + 2 * DIMC + c4);
    }
    // K into registers: lane j1=lane holds key j1; j2=lane+32 (lanes<17)
    float4 kr1[8], kr2[8];
    {
        const int j2c = min(32 + lane, 48);
        const float* kp1 = g_qkv + ((size_t)b * NTOK + lane) * QKVCOLS + DIMC + h * HDIM;
        const float* kp2 = g_qkv + ((size_t)b * NTOK + j2c ) * QKVCOLS + DIMC + h * HDIM;
        #pragma unroll
        for (int c = 0; c < 8; c++) {
            kr1[c] = *(const float4*)(kp1 + c * 4);
            kr2[c] = *(const float4*)(kp2 + c * 4);
        }
    }
    __syncthreads();

    const float* mrow0 = mask + (size_t)(b & 63) * (49 * 49);
    const float* brow0 = g_bias + ((size_t)b * NHEAD + h) * (49 * 49);
    float* attn_b = attn_out + ((size_t)b * NHEAD + h) * (49 * 49);
    const bool has2 = (lane < 17);
    const int j1 = lane, j2 = lane + 32;
    const int nrows = (warp == 0) ? 7 : 6;

    #pragma unroll 1
    for (int r = 0; r < nrows; r++) {
        const int i = warp + r * 8;
        float acc1 = 0.0f, acc2 = 0.0f;
        #pragma unroll
        for (int c = 0; c < 8; c++) {
            float4 q4 = *(const float4*)(q_s + i * 32 + c * 4);
            acc1 += q4.x * kr1[c].x + q4.y * kr1[c].y
                  + q4.z * kr1[c].z + q4.w * kr1[c].w;
            acc2 += q4.x * kr2[c].x + q4.y * kr2[c].y
                  + q4.z * kr2[c].z + q4.w * kr2[c].w;
        }
        acc1 += brow0[i * 49 + j1] + mrow0[i * 49 + j1];
        if (has2) acc2 += brow0[i * 49 + j2] + mrow0[i * 49 + j2];

        float mx = has2 ? fmaxf(acc1, acc2) : acc1;
        #pragma unroll
        for (int o = 16; o > 0; o >>= 1)
            mx = fmaxf(mx, __shfl_xor_sync(0xffffffffu, mx, o));
        float e1 = __expf(acc1 - mx);
        float e2 = has2 ? __expf(acc2 - mx) : 0.0f;
        float sum = e1 + e2;
        #pragma unroll
        for (int o = 16; o > 0; o >>= 1)
            sum += __shfl_xor_sync(0xffffffffu, sum, o);
        float inv = 1.0f / sum;
        float p1 = e1 * inv, p2 = e2 * inv;

        p_s[i * 52 + j1]    = p1;
        attn_b[i * 49 + j1] = p1;
        if (has2) { p_s[i * 52 + j2] = p2; attn_b[i * 49 + j2] = p2; }
    }
    __syncwarp();

    // P @ V: v row loaded once per warp, reused across the warp's rows
    float o[7];
    #pragma unroll
    for (int r = 0; r < 7; r++) o[r] = 0.0f;

    #pragma unroll 1
    for (int j4 = 0; j4 < 12; j4++) {
        float v0 = v_s[(j4 * 4 + 0) * 32 + lane];
        float v1 = v_s[(j4 * 4 + 1) * 32 + lane];
        float v2 = v_s[(j4 * 4 + 2) * 32 + lane];
        float v3 = v_s[(j4 * 4 + 3) * 32 + lane];
        for (int r = 0; r < nrows; r++) {
            float4 p4 = *(const float4*)&p_s[(warp + r * 8) * 52 + j4 * 4];
            o[r] += p4.x * v0 + p4.y * v1 + p4.z * v2 + p4.w * v3;
        }
    }
    {   // j = 48 remainder
        float v48 = v_s[48 * 32 + lane];
        for (int r = 0; r < nrows; r++)
            o[r] += p_s[(warp + r * 8) * 52 + 48] * v48;
    }
    for (int r = 0; r < nrows; r++) {
        int i = warp + r * 8;
        g_obuf[((size_t)b * NTOK + i) * DIMC + h * HDIM + lane] = o[r];
    }
}

// ---------------------------------------------------------------------------
extern "C" void kernel_launch(void* const* d_in, const int* in_sizes, int n_in,
                              void* d_out, int out_size)
{
    const float* x      = (const float*)d_in[0];
    const float* mask   = (const float*)d_in[1];
    const float* qkv_w  = (const float*)d_in[2];
    const float* qkv_b  = (const float*)d_in[3];
    const float* q_rpe  = (const float*)d_in[4];
    const float* k_rpe  = (const float*)d_in[5];
    const float* proj_w = (const float*)d_in[6];
    const float* proj_b = (const float*)d_in[7];
    // d_in[8] = rpe_indices: recomputed analytically in-kernel

    float* out  = (float*)d_out;
    float* attn = out + (size_t)TOKENS * DIMC;

    void* qkv_ptr  = nullptr;
    void* obuf_ptr = nullptr;
    cudaGetSymbolAddress(&qkv_ptr,  g_qkv);
    cudaGetSymbolAddress(&obuf_ptr, g_obuf);

    // K1: QKV projection (q pre-scaled)
    {
        dim3 grid(QKVCOLS / 64, TOKENS / 128);
        gemm_bias_kernel<<<grid, 128>>>(x, qkv_w, qkv_b, (float*)qkv_ptr,
                                        TOKENS, QKVCOLS, DIMC, DIMC, QSCALE);
    }
    // K2a: bias GEMM
    {
        dim3 grid(NHEAD * NTOK, B_WIN / 128);
        bias_kernel<<<grid, 256>>>(q_rpe, k_rpe);
    }
    // K2b: attention
    {
        dim3 grid(NHEAD, B_WIN);
        attn2_kernel<<<grid, 256>>>(mask, attn);
    }
    // K3: output projection
    {
        dim3 grid(DIMC / 64, TOKENS / 128);
        gemm_bias_kernel<<<grid, 128>>>((const float*)obuf_ptr, proj_w, proj_b, out,
                                        TOKENS, DIMC, DIMC, 0, 1.0f);
    }
}